// round 1
// baseline (speedup 1.0000x reference)
#include <cuda_runtime.h>
#include <math.h>

// ---------------- Problem constants ----------------
#define NREF 131072
#define NALT 32768
#define BSEG 4096
#define DDIM 128
#define FDIM 512
#define HDIM 256
#define LN_EPS 1e-5f

// ---------------- Scratch (device globals; no allocation allowed) ----------
__device__ float g_z1_ref[(size_t)NREF * HDIM];
__device__ float g_z2_ref[(size_t)NREF * HDIM];
__device__ float g_z1_alt[(size_t)NALT * HDIM];
__device__ float g_z2_alt[(size_t)NALT * HDIM];
__device__ float g_sum_ref[BSEG * HDIM];
__device__ float g_sum_alt[BSEG * HDIM];
__device__ float g_cnt_ref[BSEG];
__device__ float g_cnt_alt[BSEG];
__device__ float g_cref[BSEG * HDIM];
__device__ float g_calt[BSEG * HDIM];

// ---------------- Packed f32x2 helpers (sm_103a) ----------------
typedef unsigned long long ull;

__device__ __forceinline__ ull pk2(float lo, float hi) {
    ull r;
    asm("mov.b64 %0, {%1, %2};" : "=l"(r) : "f"(lo), "f"(hi));
    return r;
}
__device__ __forceinline__ float2 upk2(ull v) {
    float2 r;
    asm("mov.b64 {%0, %1}, %2;" : "=f"(r.x), "=f"(r.y) : "l"(v));
    return r;
}
__device__ __forceinline__ void fma2(ull &d, ull a, ull b) {
    asm("fma.rn.f32x2 %0, %1, %2, %0;" : "+l"(d) : "l"(a), "l"(b));
}

__device__ __forceinline__ float warp_sum(float v) {
#pragma unroll
    for (int o = 16; o > 0; o >>= 1) v += __shfl_xor_sync(0xffffffffu, v, o);
    return v;
}

__device__ __forceinline__ float selu_f(float x) {
    const float sc = 1.0507009873554805f;
    const float al = 1.6732632423543772f;
    return x > 0.f ? sc * x : sc * al * (expf(x) - 1.f);
}

// ---------------- Kernel 0: zero accumulators ----------------
__global__ void zero_kernel(float* __restrict__ s1, float* __restrict__ s2,
                            float* __restrict__ c1, float* __restrict__ c2) {
    int i = blockIdx.x * blockDim.x + threadIdx.x;
    if (i < BSEG * HDIM) { s1[i] = 0.f; s2[i] = 0.f; }
    if (i < BSEG)        { c1[i] = 0.f; c2[i] = 0.f; }
}

// ---------------- Kernel 1: LN1 + GEMM1 + SELU + LN2 + spill + seg-sum -----
// Block: 256 threads, 64 rows. smem: xn[64][130], wt[128][128], z2[64][256].
#define SM1_FLOATS (64 * 130 + 128 * 128 + 64 * 256)
#define SM1_BYTES (SM1_FLOATS * 4 + 64 * 4)

__global__ void __launch_bounds__(256, 1)
fwd1_kernel(const float* __restrict__ x, const int* __restrict__ seg,
            const float* __restrict__ n1w, const float* __restrict__ n1b,
            const float* __restrict__ w1, const float* __restrict__ b1,
            const float* __restrict__ n2w, const float* __restrict__ n2b,
            float* __restrict__ z1out, float* __restrict__ z2out,
            float* __restrict__ segsum, float* __restrict__ segcnt) {
    extern __shared__ float sm[];
    float* sxn = sm;                        // [64][130]
    float* swt = sxn + 64 * 130;            // [128][128]
    float* sz2 = swt + 128 * 128;           // [64][256]
    int*   ssg = (int*)(sz2 + 64 * 256);    // [64]

    const int tid = threadIdx.x;
    const int wid = tid >> 5;
    const int lane = tid & 31;
    const int ty = tid >> 4;   // 0..15
    const int tx = tid & 15;   // 0..15
    const int row0 = blockIdx.x * 64;

    // ---- Phase 1: load x rows + LayerNorm1 -> sxn (row-major, stride 130)
    {
        float4 wv = __ldg(((const float4*)n1w) + lane);
        float4 bv = __ldg(((const float4*)n1b) + lane);
#pragma unroll
        for (int t = 0; t < 8; t++) {
            int rl = wid * 8 + t;
            size_t row = (size_t)(row0 + rl);
            float4 xv = __ldg((const float4*)(x + row * DDIM + lane * 4));
            float s  = warp_sum(xv.x + xv.y + xv.z + xv.w);
            float sq = warp_sum(xv.x * xv.x + xv.y * xv.y + xv.z * xv.z + xv.w * xv.w);
            float m = s * (1.f / 128.f);
            float var = sq * (1.f / 128.f) - m * m;
            float inv = rsqrtf(var + LN_EPS);
            float* dst = &sxn[rl * 130 + lane * 4];
            dst[0] = (xv.x - m) * inv * wv.x + bv.x;
            dst[1] = (xv.y - m) * inv * wv.y + bv.y;
            dst[2] = (xv.z - m) * inv * wv.z + bv.z;
            dst[3] = (xv.w - m) * inv * wv.w + bv.w;
        }
    }

    // ---- Phase 2: GEMM1 in 4 N-chunks of 128, SELU, route z1->gmem z2->smem
#pragma unroll 1
    for (int c = 0; c < 4; c++) {
        __syncthreads();
        // load w1 chunk [128][128] into swt, coalesced float4
        {
            const int cbase = c * 128;
#pragma unroll
            for (int q = 0; q < 16; q++) {
                int f4 = q * 256 + tid;          // 0..4095
                int k = f4 >> 5;                 // 0..127
                int n4 = f4 & 31;                // 0..31
                *(float4*)(&swt[k * 128 + n4 * 4]) =
                    __ldg((const float4*)(w1 + (size_t)k * FDIM + cbase + n4 * 4));
            }
        }
        __syncthreads();

        ull acc[4][4];
#pragma unroll
        for (int i = 0; i < 4; i++)
#pragma unroll
            for (int j = 0; j < 4; j++) acc[i][j] = 0ULL;

#pragma unroll 8
        for (int k = 0; k < 128; k++) {
            const float* wr = &swt[k * 128 + tx * 8];
            float4 bA = *(const float4*)wr;
            float4 bB = *(const float4*)(wr + 4);
            ull b0 = pk2(bA.x, bA.y), b1v = pk2(bA.z, bA.w);
            ull b2v = pk2(bB.x, bB.y), b3v = pk2(bB.z, bB.w);
#pragma unroll
            for (int i = 0; i < 4; i++) {
                float av = sxn[(ty * 4 + i) * 130 + k];
                ull a2 = pk2(av, av);
                fma2(acc[i][0], a2, b0);
                fma2(acc[i][1], a2, b1v);
                fma2(acc[i][2], a2, b2v);
                fma2(acc[i][3], a2, b3v);
            }
        }

        // epilogue: bias + SELU
        const int cbase = c * 128;
        float4 bb0 = __ldg((const float4*)(b1 + cbase + tx * 8));
        float4 bb1 = __ldg((const float4*)(b1 + cbase + tx * 8 + 4));
#pragma unroll
        for (int i = 0; i < 4; i++) {
            int rl = ty * 4 + i;
            float2 p0 = upk2(acc[i][0]), p1 = upk2(acc[i][1]);
            float2 p2 = upk2(acc[i][2]), p3 = upk2(acc[i][3]);
            float4 o0, o1;
            o0.x = selu_f(p0.x + bb0.x); o0.y = selu_f(p0.y + bb0.y);
            o0.z = selu_f(p1.x + bb0.z); o0.w = selu_f(p1.y + bb0.w);
            o1.x = selu_f(p2.x + bb1.x); o1.y = selu_f(p2.y + bb1.y);
            o1.z = selu_f(p3.x + bb1.z); o1.w = selu_f(p3.y + bb1.w);
            if (c < 2) {
                size_t row = (size_t)(row0 + rl);
                float* dst = z1out + row * HDIM + cbase + tx * 8;
                *(float4*)dst = o0;
                *(float4*)(dst + 4) = o1;
            } else {
                float* dst = &sz2[rl * 256 + (c - 2) * 128 + tx * 8];
                *(float4*)dst = o0;
                *(float4*)(dst + 4) = o1;
            }
        }
    }

    __syncthreads();

    // ---- Phase 3: LayerNorm2 over z2 rows (256 wide), write gmem + smem
    {
        float wreg[8], breg[8];
#pragma unroll
        for (int u = 0; u < 8; u++) {
            wreg[u] = __ldg(n2w + lane + 32 * u);
            breg[u] = __ldg(n2b + lane + 32 * u);
        }
#pragma unroll
        for (int t = 0; t < 8; t++) {
            int rl = wid * 8 + t;
            float v[8];
            float s = 0.f, sq = 0.f;
#pragma unroll
            for (int u = 0; u < 8; u++) {
                v[u] = sz2[rl * 256 + lane + 32 * u];
                s += v[u];
                sq += v[u] * v[u];
            }
            s = warp_sum(s);
            sq = warp_sum(sq);
            float m = s * (1.f / 256.f);
            float var = sq * (1.f / 256.f) - m * m;
            float inv = rsqrtf(var + LN_EPS);
            size_t row = (size_t)(row0 + rl);
#pragma unroll
            for (int u = 0; u < 8; u++) {
                float y = (v[u] - m) * inv * wreg[u] + breg[u];
                z2out[row * HDIM + lane + 32 * u] = y;
                sz2[rl * 256 + lane + 32 * u] = y;
            }
        }
    }

    if (tid < 64) ssg[tid] = __ldg(seg + row0 + tid);
    __syncthreads();

    // ---- Phase 4: run-length aggregated segment sums (segs sorted)
    {
        int col = tid;  // 0..255 == HDIM
        float acc = 0.f;
        int cur = ssg[0];
#pragma unroll 1
        for (int r = 0; r < 64; r++) {
            int s = ssg[r];
            if (s != cur) {
                atomicAdd(&segsum[(size_t)cur * HDIM + col], acc);
                acc = 0.f;
                cur = s;
            }
            acc += sz2[r * 256 + col];
        }
        atomicAdd(&segsum[(size_t)cur * HDIM + col], acc);
    }
    if (tid == 0) {
        float acc = 0.f;
        int cur = ssg[0];
        for (int r = 0; r < 64; r++) {
            int s = ssg[r];
            if (s != cur) {
                atomicAdd(&segcnt[cur], acc);
                acc = 0.f;
                cur = s;
            }
            acc += 1.f;
        }
        atomicAdd(&segcnt[cur], acc);
    }
}

// ---------------- Kernel 2: per-(batch,h) gate coefficients ----------------
__global__ void coeff_kernel(const float* __restrict__ sum_r, const float* __restrict__ cnt_r,
                             const float* __restrict__ sum_a, const float* __restrict__ cnt_a,
                             const float* __restrict__ ref_reg, const float* __restrict__ reg_w_pre,
                             const float* __restrict__ beta_ref, const float* __restrict__ beta_alt,
                             const float* __restrict__ gamma,
                             float* __restrict__ cref, float* __restrict__ calt) {
    int idx = blockIdx.x * blockDim.x + threadIdx.x;
    if (idx >= BSEG * HDIM) return;
    int b = idx >> 8;
    int h = idx & 255;
    float rw = expf(reg_w_pre[0]) + 0.25f;
    float rmf = (sum_r[idx] + rw * ref_reg[h]) / (cnt_r[b] + rw);
    float amf = sum_a[idx] / fmaxf(cnt_a[b], 1.f);
    cref[idx] = beta_ref[0] * rmf;
    calt[idx] = beta_alt[0] * amf + gamma[0] * rmf;
}

// ---------------- Kernel 3: gate + GEMM2 + residual ----------------
// Block: 256 threads, 64 rows. smem: w2[256][128] + g[64][260].
#define SM2_FLOATS (256 * 128 + 64 * 260)
#define SM2_BYTES (SM2_FLOATS * 4 + 64 * 4)

__global__ void __launch_bounds__(256, 1)
fwd2_kernel(const float* __restrict__ x, const int* __restrict__ seg,
            const float* __restrict__ z1, const float* __restrict__ z2,
            const float* __restrict__ ctab, const float* __restrict__ alpha_p,
            const float* __restrict__ w2, const float* __restrict__ b2,
            float* __restrict__ out) {
    extern __shared__ float sm[];
    float* sw2 = sm;                        // [256][128]
    float* sg  = sw2 + 256 * 128;           // [64][260]
    int*   ssg = (int*)(sg + 64 * 260);     // [64]

    const int tid = threadIdx.x;
    const int ty = tid >> 4;
    const int tx = tid & 15;
    const int row0 = blockIdx.x * 64;

    // load full W2 (256x128 = exactly 32768 floats), flat copy
#pragma unroll
    for (int q = 0; q < 32; q++) {
        int f4 = q * 256 + tid;
        ((float4*)sw2)[f4] = __ldg(((const float4*)w2) + f4);
    }
    if (tid < 64) ssg[tid] = __ldg(seg + row0 + tid);
    __syncthreads();

    // build gated activations g = z1 * (z2*alpha + 1 + c[seg])
    const float alpha = __ldg(alpha_p);
#pragma unroll 4
    for (int it = 0; it < 64; it++) {
        size_t row = (size_t)(row0 + it);
        float z1v = __ldg(z1 + row * HDIM + tid);
        float z2v = __ldg(z2 + row * HDIM + tid);
        float cc = __ldg(ctab + (size_t)ssg[it] * HDIM + tid);
        sg[it * 260 + tid] = z1v * fmaf(z2v, alpha, 1.f + cc);
    }
    __syncthreads();

    // GEMM: out[64][128] = g[64][256] @ w2[256][128]
    ull acc[4][4];
#pragma unroll
    for (int i = 0; i < 4; i++)
#pragma unroll
        for (int j = 0; j < 4; j++) acc[i][j] = 0ULL;

#pragma unroll 8
    for (int k = 0; k < 256; k++) {
        const float* wr = &sw2[k * 128 + tx * 8];
        float4 bA = *(const float4*)wr;
        float4 bB = *(const float4*)(wr + 4);
        ull b0 = pk2(bA.x, bA.y), b1v = pk2(bA.z, bA.w);
        ull b2v = pk2(bB.x, bB.y), b3v = pk2(bB.z, bB.w);
#pragma unroll
        for (int i = 0; i < 4; i++) {
            float av = sg[(ty * 4 + i) * 260 + k];
            ull a2 = pk2(av, av);
            fma2(acc[i][0], a2, b0);
            fma2(acc[i][1], a2, b1v);
            fma2(acc[i][2], a2, b2v);
            fma2(acc[i][3], a2, b3v);
        }
    }

    // epilogue: residual + bias
    float4 bb0 = __ldg((const float4*)(b2 + tx * 8));
    float4 bb1 = __ldg((const float4*)(b2 + tx * 8 + 4));
#pragma unroll
    for (int i = 0; i < 4; i++) {
        size_t row = (size_t)(row0 + ty * 4 + i);
        const float* xs = x + row * DDIM + tx * 8;
        float4 x0 = __ldg((const float4*)xs);
        float4 x1 = __ldg((const float4*)(xs + 4));
        float2 p0 = upk2(acc[i][0]), p1 = upk2(acc[i][1]);
        float2 p2 = upk2(acc[i][2]), p3 = upk2(acc[i][3]);
        float4 o0, o1;
        o0.x = x0.x + p0.x + bb0.x; o0.y = x0.y + p0.y + bb0.y;
        o0.z = x0.z + p1.x + bb0.z; o0.w = x0.w + p1.y + bb0.w;
        o1.x = x1.x + p2.x + bb1.x; o1.y = x1.y + p2.y + bb1.y;
        o1.z = x1.z + p3.x + bb1.z; o1.w = x1.w + p3.y + bb1.w;
        float* dst = out + row * DDIM + tx * 8;
        *(float4*)dst = o0;
        *(float4*)(dst + 4) = o1;
    }
}

// ---------------- Launch ----------------
extern "C" void kernel_launch(void* const* d_in, const int* in_sizes, int n_in,
                              void* d_out, int out_size) {
    const float* ref_flat = (const float*)d_in[0];
    const float* alt_flat = (const float*)d_in[1];
    const int*   ref_seg  = (const int*)d_in[2];
    const int*   alt_seg  = (const int*)d_in[3];
    const float* norm1_w  = (const float*)d_in[4];
    const float* norm1_b  = (const float*)d_in[5];
    const float* w1_ref   = (const float*)d_in[6];
    const float* b1_ref   = (const float*)d_in[7];
    const float* w1_alt   = (const float*)d_in[8];
    const float* b1_alt   = (const float*)d_in[9];
    const float* norm2_w  = (const float*)d_in[10];
    const float* norm2_b  = (const float*)d_in[11];
    const float* alpha_ref = (const float*)d_in[12];
    const float* alpha_alt = (const float*)d_in[13];
    const float* beta_ref  = (const float*)d_in[14];
    const float* beta_alt  = (const float*)d_in[15];
    const float* gamma     = (const float*)d_in[16];
    const float* ref_regularizer = (const float*)d_in[17];
    const float* reg_w_pre = (const float*)d_in[18];
    const float* w2_ref    = (const float*)d_in[19];
    const float* b2_ref    = (const float*)d_in[20];
    const float* w2_alt    = (const float*)d_in[21];
    const float* b2_alt    = (const float*)d_in[22];

    float* out_r = (float*)d_out;
    float* out_a = out_r + (size_t)NREF * DDIM;

    float *pz1r, *pz2r, *pz1a, *pz2a, *psr, *psa, *pcr, *pca, *pcref, *pcalt;
    cudaGetSymbolAddress((void**)&pz1r, g_z1_ref);
    cudaGetSymbolAddress((void**)&pz2r, g_z2_ref);
    cudaGetSymbolAddress((void**)&pz1a, g_z1_alt);
    cudaGetSymbolAddress((void**)&pz2a, g_z2_alt);
    cudaGetSymbolAddress((void**)&psr,  g_sum_ref);
    cudaGetSymbolAddress((void**)&psa,  g_sum_alt);
    cudaGetSymbolAddress((void**)&pcr,  g_cnt_ref);
    cudaGetSymbolAddress((void**)&pca,  g_cnt_alt);
    cudaGetSymbolAddress((void**)&pcref, g_cref);
    cudaGetSymbolAddress((void**)&pcalt, g_calt);

    cudaFuncSetAttribute(fwd1_kernel, cudaFuncAttributeMaxDynamicSharedMemorySize, SM1_BYTES);
    cudaFuncSetAttribute(fwd2_kernel, cudaFuncAttributeMaxDynamicSharedMemorySize, SM2_BYTES);

    zero_kernel<<<(BSEG * HDIM + 255) / 256, 256>>>(psr, psa, pcr, pca);

    fwd1_kernel<<<NREF / 64, 256, SM1_BYTES>>>(ref_flat, ref_seg, norm1_w, norm1_b,
                                               w1_ref, b1_ref, norm2_w, norm2_b,
                                               pz1r, pz2r, psr, pcr);
    fwd1_kernel<<<NALT / 64, 256, SM1_BYTES>>>(alt_flat, alt_seg, norm1_w, norm1_b,
                                               w1_alt, b1_alt, norm2_w, norm2_b,
                                               pz1a, pz2a, psa, pca);

    coeff_kernel<<<(BSEG * HDIM + 255) / 256, 256>>>(psr, pcr, psa, pca,
                                                     ref_regularizer, reg_w_pre,
                                                     beta_ref, beta_alt, gamma,
                                                     pcref, pcalt);

    fwd2_kernel<<<NREF / 64, 256, SM2_BYTES>>>(ref_flat, ref_seg, pz1r, pz2r,
                                               pcref, alpha_ref, w2_ref, b2_ref, out_r);
    fwd2_kernel<<<NALT / 64, 256, SM2_BYTES>>>(alt_flat, alt_seg, pz1a, pz2a,
                                               pcalt, alpha_alt, w2_alt, b2_alt, out_a);
}

// round 2
// speedup vs baseline: 1.0099x; 1.0099x over previous
#include <cuda_runtime.h>
#include <math.h>

// ---------------- Problem constants ----------------
#define NREF 131072
#define NALT 32768
#define BSEG 4096
#define DDIM 128
#define FDIM 512
#define HDIM 256
#define LN_EPS 1e-5f

// ---------------- Scratch (device globals; no allocation allowed) ----------
__device__ float g_z1_ref[(size_t)NREF * HDIM];
__device__ float g_z2_ref[(size_t)NREF * HDIM];
__device__ float g_z1_alt[(size_t)NALT * HDIM];
__device__ float g_z2_alt[(size_t)NALT * HDIM];
__device__ float g_sum_ref[BSEG * HDIM];
__device__ float g_sum_alt[BSEG * HDIM];
__device__ float g_cnt_ref[BSEG];
__device__ float g_cnt_alt[BSEG];
__device__ float g_cref[BSEG * HDIM];
__device__ float g_calt[BSEG * HDIM];

// ---------------- Packed f32x2 helpers (sm_103a) ----------------
typedef unsigned long long ull;

__device__ __forceinline__ ull pk2(float lo, float hi) {
    ull r;
    asm("mov.b64 %0, {%1, %2};" : "=l"(r) : "f"(lo), "f"(hi));
    return r;
}
__device__ __forceinline__ float2 upk2(ull v) {
    float2 r;
    asm("mov.b64 {%0, %1}, %2;" : "=f"(r.x), "=f"(r.y) : "l"(v));
    return r;
}
__device__ __forceinline__ void fma2(ull &d, ull a, ull b) {
    asm("fma.rn.f32x2 %0, %1, %2, %0;" : "+l"(d) : "l"(a), "l"(b));
}

__device__ __forceinline__ float warp_sum(float v) {
#pragma unroll
    for (int o = 16; o > 0; o >>= 1) v += __shfl_xor_sync(0xffffffffu, v, o);
    return v;
}

__device__ __forceinline__ float selu_f(float x) {
    const float sc = 1.0507009873554805f;
    const float al = 1.6732632423543772f;
    return x > 0.f ? sc * x : sc * al * (expf(x) - 1.f);
}

// ---------------- Kernel 0: zero accumulators ----------------
__global__ void zero_kernel(float* __restrict__ s1, float* __restrict__ s2,
                            float* __restrict__ c1, float* __restrict__ c2) {
    int i = blockIdx.x * blockDim.x + threadIdx.x;
    if (i < BSEG * HDIM) { s1[i] = 0.f; s2[i] = 0.f; }
    if (i < BSEG)        { c1[i] = 0.f; c2[i] = 0.f; }
}

// ---------------- Kernel 1: LN1 + GEMM1 + SELU + LN2 + spill + seg-sum -----
// Block: 256 threads, 64 rows. smem: xn[64][130], wt[128][128], z2[64][256].
#define SM1_FLOATS (64 * 130 + 128 * 128 + 64 * 256)
#define SM1_BYTES (SM1_FLOATS * 4 + 64 * 4)

__global__ void __launch_bounds__(256, 1)
fwd1_kernel(const float* __restrict__ x, const int* __restrict__ seg,
            const float* __restrict__ n1w, const float* __restrict__ n1b,
            const float* __restrict__ w1, const float* __restrict__ b1,
            const float* __restrict__ n2w, const float* __restrict__ n2b,
            float* __restrict__ z1out, float* __restrict__ z2out,
            float* __restrict__ segsum, float* __restrict__ segcnt) {
    extern __shared__ float sm[];
    float* sxn = sm;                        // [64][130]
    float* swt = sxn + 64 * 130;            // [128][128]
    float* sz2 = swt + 128 * 128;           // [64][256]
    int*   ssg = (int*)(sz2 + 64 * 256);    // [64]

    const int tid = threadIdx.x;
    const int wid = tid >> 5;
    const int lane = tid & 31;
    const int ty = tid >> 4;   // 0..15
    const int tx = tid & 15;   // 0..15
    const int row0 = blockIdx.x * 64;

    // ---- Phase 1: load x rows + LayerNorm1 -> sxn (row-major, stride 130)
    {
        float4 wv = __ldg(((const float4*)n1w) + lane);
        float4 bv = __ldg(((const float4*)n1b) + lane);
#pragma unroll
        for (int t = 0; t < 8; t++) {
            int rl = wid * 8 + t;
            size_t row = (size_t)(row0 + rl);
            float4 xv = __ldg((const float4*)(x + row * DDIM + lane * 4));
            float s  = warp_sum(xv.x + xv.y + xv.z + xv.w);
            float sq = warp_sum(xv.x * xv.x + xv.y * xv.y + xv.z * xv.z + xv.w * xv.w);
            float m = s * (1.f / 128.f);
            float var = sq * (1.f / 128.f) - m * m;
            float inv = rsqrtf(var + LN_EPS);
            float* dst = &sxn[rl * 130 + lane * 4];
            dst[0] = (xv.x - m) * inv * wv.x + bv.x;
            dst[1] = (xv.y - m) * inv * wv.y + bv.y;
            dst[2] = (xv.z - m) * inv * wv.z + bv.z;
            dst[3] = (xv.w - m) * inv * wv.w + bv.w;
        }
    }

    // ---- Phase 2: GEMM1 in 4 N-chunks of 128, SELU, route z1->gmem z2->smem
#pragma unroll 1
    for (int c = 0; c < 4; c++) {
        __syncthreads();
        // load w1 chunk [128][128] into swt, coalesced float4
        {
            const int cbase = c * 128;
#pragma unroll
            for (int q = 0; q < 16; q++) {
                int f4 = q * 256 + tid;          // 0..4095
                int k = f4 >> 5;                 // 0..127
                int n4 = f4 & 31;                // 0..31
                *(float4*)(&swt[k * 128 + n4 * 4]) =
                    __ldg((const float4*)(w1 + (size_t)k * FDIM + cbase + n4 * 4));
            }
        }
        __syncthreads();

        ull acc[4][4];
#pragma unroll
        for (int i = 0; i < 4; i++)
#pragma unroll
            for (int j = 0; j < 4; j++) acc[i][j] = 0ULL;

#pragma unroll 8
        for (int k = 0; k < 128; k++) {
            const float* wr = &swt[k * 128 + tx * 8];
            float4 bA = *(const float4*)wr;
            float4 bB = *(const float4*)(wr + 4);
            ull b0 = pk2(bA.x, bA.y), b1v = pk2(bA.z, bA.w);
            ull b2v = pk2(bB.x, bB.y), b3v = pk2(bB.z, bB.w);
#pragma unroll
            for (int i = 0; i < 4; i++) {
                float av = sxn[(ty * 4 + i) * 130 + k];
                ull a2 = pk2(av, av);
                fma2(acc[i][0], a2, b0);
                fma2(acc[i][1], a2, b1v);
                fma2(acc[i][2], a2, b2v);
                fma2(acc[i][3], a2, b3v);
            }
        }

        // epilogue: bias + SELU
        const int cbase = c * 128;
        float4 bb0 = __ldg((const float4*)(b1 + cbase + tx * 8));
        float4 bb1 = __ldg((const float4*)(b1 + cbase + tx * 8 + 4));
#pragma unroll
        for (int i = 0; i < 4; i++) {
            int rl = ty * 4 + i;
            float2 p0 = upk2(acc[i][0]), p1 = upk2(acc[i][1]);
            float2 p2 = upk2(acc[i][2]), p3 = upk2(acc[i][3]);
            float4 o0, o1;
            o0.x = selu_f(p0.x + bb0.x); o0.y = selu_f(p0.y + bb0.y);
            o0.z = selu_f(p1.x + bb0.z); o0.w = selu_f(p1.y + bb0.w);
            o1.x = selu_f(p2.x + bb1.x); o1.y = selu_f(p2.y + bb1.y);
            o1.z = selu_f(p3.x + bb1.z); o1.w = selu_f(p3.y + bb1.w);
            if (c < 2) {
                size_t row = (size_t)(row0 + rl);
                float* dst = z1out + row * HDIM + cbase + tx * 8;
                *(float4*)dst = o0;
                *(float4*)(dst + 4) = o1;
            } else {
                float* dst = &sz2[rl * 256 + (c - 2) * 128 + tx * 8];
                *(float4*)dst = o0;
                *(float4*)(dst + 4) = o1;
            }
        }
    }

    __syncthreads();

    // ---- Phase 3: LayerNorm2 over z2 rows (256 wide), write gmem + smem
    {
        float wreg[8], breg[8];
#pragma unroll
        for (int u = 0; u < 8; u++) {
            wreg[u] = __ldg(n2w + lane + 32 * u);
            breg[u] = __ldg(n2b + lane + 32 * u);
        }
#pragma unroll
        for (int t = 0; t < 8; t++) {
            int rl = wid * 8 + t;
            float v[8];
            float s = 0.f, sq = 0.f;
#pragma unroll
            for (int u = 0; u < 8; u++) {
                v[u] = sz2[rl * 256 + lane + 32 * u];
                s += v[u];
                sq += v[u] * v[u];
            }
            s = warp_sum(s);
            sq = warp_sum(sq);
            float m = s * (1.f / 256.f);
            float var = sq * (1.f / 256.f) - m * m;
            float inv = rsqrtf(var + LN_EPS);
            size_t row = (size_t)(row0 + rl);
#pragma unroll
            for (int u = 0; u < 8; u++) {
                float y = (v[u] - m) * inv * wreg[u] + breg[u];
                z2out[row * HDIM + lane + 32 * u] = y;
                sz2[rl * 256 + lane + 32 * u] = y;
            }
        }
    }

    if (tid < 64) ssg[tid] = __ldg(seg + row0 + tid);
    __syncthreads();

    // ---- Phase 4: run-length aggregated segment sums (segs sorted)
    {
        int col = tid;  // 0..255 == HDIM
        float acc = 0.f;
        int cur = ssg[0];
#pragma unroll 1
        for (int r = 0; r < 64; r++) {
            int s = ssg[r];
            if (s != cur) {
                atomicAdd(&segsum[(size_t)cur * HDIM + col], acc);
                acc = 0.f;
                cur = s;
            }
            acc += sz2[r * 256 + col];
        }
        atomicAdd(&segsum[(size_t)cur * HDIM + col], acc);
    }
    if (tid == 0) {
        float acc = 0.f;
        int cur = ssg[0];
        for (int r = 0; r < 64; r++) {
            int s = ssg[r];
            if (s != cur) {
                atomicAdd(&segcnt[cur], acc);
                acc = 0.f;
                cur = s;
            }
            acc += 1.f;
        }
        atomicAdd(&segcnt[cur], acc);
    }
}

// ---------------- Kernel 2: per-(batch,h) gate coefficients ----------------
__global__ void coeff_kernel(const float* __restrict__ sum_r, const float* __restrict__ cnt_r,
                             const float* __restrict__ sum_a, const float* __restrict__ cnt_a,
                             const float* __restrict__ ref_reg, const float* __restrict__ reg_w_pre,
                             const float* __restrict__ beta_ref, const float* __restrict__ beta_alt,
                             const float* __restrict__ gamma,
                             float* __restrict__ cref, float* __restrict__ calt) {
    int idx = blockIdx.x * blockDim.x + threadIdx.x;
    if (idx >= BSEG * HDIM) return;
    int b = idx >> 8;
    int h = idx & 255;
    float rw = expf(reg_w_pre[0]) + 0.25f;
    float rmf = (sum_r[idx] + rw * ref_reg[h]) / (cnt_r[b] + rw);
    float amf = sum_a[idx] / fmaxf(cnt_a[b], 1.f);
    cref[idx] = beta_ref[0] * rmf;
    calt[idx] = beta_alt[0] * amf + gamma[0] * rmf;
}

// ---------------- Kernel 3: gate + GEMM2 + residual ----------------
// Block: 256 threads, 64 rows. smem: w2[256][128] + g[64][260].
#define SM2_FLOATS (256 * 128 + 64 * 260)
#define SM2_BYTES (SM2_FLOATS * 4 + 64 * 4)

__global__ void __launch_bounds__(256, 1)
fwd2_kernel(const float* __restrict__ x, const int* __restrict__ seg,
            const float* __restrict__ z1, const float* __restrict__ z2,
            const float* __restrict__ ctab, const float* __restrict__ alpha_p,
            const float* __restrict__ w2, const float* __restrict__ b2,
            float* __restrict__ out) {
    extern __shared__ float sm[];
    float* sw2 = sm;                        // [256][128]
    float* sg  = sw2 + 256 * 128;           // [64][260]
    int*   ssg = (int*)(sg + 64 * 260);     // [64]

    const int tid = threadIdx.x;
    const int ty = tid >> 4;
    const int tx = tid & 15;
    const int row0 = blockIdx.x * 64;

    // load full W2 (256x128 = exactly 32768 floats), flat copy
#pragma unroll
    for (int q = 0; q < 32; q++) {
        int f4 = q * 256 + tid;
        ((float4*)sw2)[f4] = __ldg(((const float4*)w2) + f4);
    }
    if (tid < 64) ssg[tid] = __ldg(seg + row0 + tid);
    __syncthreads();

    // build gated activations g = z1 * (z2*alpha + 1 + c[seg])
    const float alpha = __ldg(alpha_p);
#pragma unroll 4
    for (int it = 0; it < 64; it++) {
        size_t row = (size_t)(row0 + it);
        float z1v = __ldg(z1 + row * HDIM + tid);
        float z2v = __ldg(z2 + row * HDIM + tid);
        float cc = __ldg(ctab + (size_t)ssg[it] * HDIM + tid);
        sg[it * 260 + tid] = z1v * fmaf(z2v, alpha, 1.f + cc);
    }
    __syncthreads();

    // GEMM: out[64][128] = g[64][256] @ w2[256][128]
    ull acc[4][4];
#pragma unroll
    for (int i = 0; i < 4; i++)
#pragma unroll
        for (int j = 0; j < 4; j++) acc[i][j] = 0ULL;

#pragma unroll 8
    for (int k = 0; k < 256; k++) {
        const float* wr = &sw2[k * 128 + tx * 8];
        float4 bA = *(const float4*)wr;
        float4 bB = *(const float4*)(wr + 4);
        ull b0 = pk2(bA.x, bA.y), b1v = pk2(bA.z, bA.w);
        ull b2v = pk2(bB.x, bB.y), b3v = pk2(bB.z, bB.w);
#pragma unroll
        for (int i = 0; i < 4; i++) {
            float av = sg[(ty * 4 + i) * 260 + k];
            ull a2 = pk2(av, av);
            fma2(acc[i][0], a2, b0);
            fma2(acc[i][1], a2, b1v);
            fma2(acc[i][2], a2, b2v);
            fma2(acc[i][3], a2, b3v);
        }
    }

    // epilogue: residual + bias
    float4 bb0 = __ldg((const float4*)(b2 + tx * 8));
    float4 bb1 = __ldg((const float4*)(b2 + tx * 8 + 4));
#pragma unroll
    for (int i = 0; i < 4; i++) {
        size_t row = (size_t)(row0 + ty * 4 + i);
        const float* xs = x + row * DDIM + tx * 8;
        float4 x0 = __ldg((const float4*)xs);
        float4 x1 = __ldg((const float4*)(xs + 4));
        float2 p0 = upk2(acc[i][0]), p1 = upk2(acc[i][1]);
        float2 p2 = upk2(acc[i][2]), p3 = upk2(acc[i][3]);
        float4 o0, o1;
        o0.x = x0.x + p0.x + bb0.x; o0.y = x0.y + p0.y + bb0.y;
        o0.z = x0.z + p1.x + bb0.z; o0.w = x0.w + p1.y + bb0.w;
        o1.x = x1.x + p2.x + bb1.x; o1.y = x1.y + p2.y + bb1.y;
        o1.z = x1.z + p3.x + bb1.z; o1.w = x1.w + p3.y + bb1.w;
        float* dst = out + row * DDIM + tx * 8;
        *(float4*)dst = o0;
        *(float4*)(dst + 4) = o1;
    }
}

// ---------------- Launch ----------------
extern "C" void kernel_launch(void* const* d_in, const int* in_sizes, int n_in,
                              void* d_out, int out_size) {
    const float* ref_flat = (const float*)d_in[0];
    const float* alt_flat = (const float*)d_in[1];
    const int*   ref_seg  = (const int*)d_in[2];
    const int*   alt_seg  = (const int*)d_in[3];
    const float* norm1_w  = (const float*)d_in[4];
    const float* norm1_b  = (const float*)d_in[5];
    const float* w1_ref   = (const float*)d_in[6];
    const float* b1_ref   = (const float*)d_in[7];
    const float* w1_alt   = (const float*)d_in[8];
    const float* b1_alt   = (const float*)d_in[9];
    const float* norm2_w  = (const float*)d_in[10];
    const float* norm2_b  = (const float*)d_in[11];
    const float* alpha_ref = (const float*)d_in[12];
    const float* alpha_alt = (const float*)d_in[13];
    const float* beta_ref  = (const float*)d_in[14];
    const float* beta_alt  = (const float*)d_in[15];
    const float* gamma     = (const float*)d_in[16];
    const float* ref_regularizer = (const float*)d_in[17];
    const float* reg_w_pre = (const float*)d_in[18];
    const float* w2_ref    = (const float*)d_in[19];
    const float* b2_ref    = (const float*)d_in[20];
    const float* w2_alt    = (const float*)d_in[21];
    const float* b2_alt    = (const float*)d_in[22];

    float* out_r = (float*)d_out;
    float* out_a = out_r + (size_t)NREF * DDIM;

    float *pz1r, *pz2r, *pz1a, *pz2a, *psr, *psa, *pcr, *pca, *pcref, *pcalt;
    cudaGetSymbolAddress((void**)&pz1r, g_z1_ref);
    cudaGetSymbolAddress((void**)&pz2r, g_z2_ref);
    cudaGetSymbolAddress((void**)&pz1a, g_z1_alt);
    cudaGetSymbolAddress((void**)&pz2a, g_z2_alt);
    cudaGetSymbolAddress((void**)&psr,  g_sum_ref);
    cudaGetSymbolAddress((void**)&psa,  g_sum_alt);
    cudaGetSymbolAddress((void**)&pcr,  g_cnt_ref);
    cudaGetSymbolAddress((void**)&pca,  g_cnt_alt);
    cudaGetSymbolAddress((void**)&pcref, g_cref);
    cudaGetSymbolAddress((void**)&pcalt, g_calt);

    cudaFuncSetAttribute(fwd1_kernel, cudaFuncAttributeMaxDynamicSharedMemorySize, SM1_BYTES);
    cudaFuncSetAttribute(fwd2_kernel, cudaFuncAttributeMaxDynamicSharedMemorySize, SM2_BYTES);

    zero_kernel<<<(BSEG * HDIM + 255) / 256, 256>>>(psr, psa, pcr, pca);

    fwd1_kernel<<<NREF / 64, 256, SM1_BYTES>>>(ref_flat, ref_seg, norm1_w, norm1_b,
                                               w1_ref, b1_ref, norm2_w, norm2_b,
                                               pz1r, pz2r, psr, pcr);
    fwd1_kernel<<<NALT / 64, 256, SM1_BYTES>>>(alt_flat, alt_seg, norm1_w, norm1_b,
                                               w1_alt, b1_alt, norm2_w, norm2_b,
                                               pz1a, pz2a, psa, pca);

    coeff_kernel<<<(BSEG * HDIM + 255) / 256, 256>>>(psr, pcr, psa, pca,
                                                     ref_regularizer, reg_w_pre,
                                                     beta_ref, beta_alt, gamma,
                                                     pcref, pcalt);

    fwd2_kernel<<<NREF / 64, 256, SM2_BYTES>>>(ref_flat, ref_seg, pz1r, pz2r,
                                               pcref, alpha_ref, w2_ref, b2_ref, out_r);
    fwd2_kernel<<<NALT / 64, 256, SM2_BYTES>>>(alt_flat, alt_seg, pz1a, pz2a,
                                               pcalt, alpha_alt, w2_alt, b2_alt, out_a);
}

// round 3
// speedup vs baseline: 1.5502x; 1.5350x over previous
#include <cuda_runtime.h>
#include <math.h>

// ---------------- Problem constants ----------------
#define NREF 131072
#define NALT 32768
#define BSEG 4096
#define DDIM 128
#define FDIM 512
#define HDIM 256
#define LN_EPS 1e-5f

// smem strides (floats) chosen for conflict-free mma fragment access:
//   A (row-major m×k): stride%32==4 -> bank = 4*row+col pattern
//   B ([k][n]):        stride%32==8 -> bank = 8*k+n pattern
#define S_XN 132
#define S_WT 136
#define S_Z2 260

// ---------------- Scratch (device globals; no allocation allowed) ----------
__device__ float g_z1_ref[(size_t)NREF * HDIM];
__device__ float g_z2_ref[(size_t)NREF * HDIM];
__device__ float g_z1_alt[(size_t)NALT * HDIM];
__device__ float g_z2_alt[(size_t)NALT * HDIM];
__device__ float g_sum_ref[BSEG * HDIM];
__device__ float g_sum_alt[BSEG * HDIM];
__device__ float g_cnt_ref[BSEG];
__device__ float g_cnt_alt[BSEG];
__device__ float g_cref[BSEG * HDIM];
__device__ float g_calt[BSEG * HDIM];

// ---------------- Helpers ----------------
__device__ __forceinline__ unsigned tf32_rna(float f) {
    unsigned u;
    asm("cvt.rna.tf32.f32 %0, %1;" : "=r"(u) : "f"(f));
    return u;
}
__device__ __forceinline__ float tf32f(float f) {
    return __uint_as_float(tf32_rna(f));
}

__device__ __forceinline__ void mma_tf32(float* c, const unsigned* a, unsigned b0, unsigned b1) {
    asm volatile(
        "mma.sync.aligned.m16n8k8.row.col.f32.tf32.tf32.f32 "
        "{%0,%1,%2,%3}, {%4,%5,%6,%7}, {%8,%9}, {%0,%1,%2,%3};"
        : "+f"(c[0]), "+f"(c[1]), "+f"(c[2]), "+f"(c[3])
        : "r"(a[0]), "r"(a[1]), "r"(a[2]), "r"(a[3]), "r"(b0), "r"(b1));
}

__device__ __forceinline__ float warp_sum(float v) {
#pragma unroll
    for (int o = 16; o > 0; o >>= 1) v += __shfl_xor_sync(0xffffffffu, v, o);
    return v;
}

__device__ __forceinline__ float selu_f(float x) {
    const float sc = 1.0507009873554805f;
    const float al = 1.6732632423543772f;
    return x > 0.f ? sc * x : sc * al * (expf(x) - 1.f);
}

// ---------------- Kernel 0: zero accumulators ----------------
__global__ void zero_kernel(float* __restrict__ s1, float* __restrict__ s2,
                            float* __restrict__ c1, float* __restrict__ c2) {
    int i = blockIdx.x * blockDim.x + threadIdx.x;
    if (i < BSEG * HDIM) { s1[i] = 0.f; s2[i] = 0.f; }
    if (i < BSEG)        { c1[i] = 0.f; c2[i] = 0.f; }
}

// ---------------- Kernel 1: LN1 + GEMM1(tf32 mma) + SELU + LN2 + seg-sum ---
// Block: 256 threads (8 warps), 64 rows.
#define SM1_FLOATS (64 * S_XN + 128 * S_WT + 64 * S_Z2)
#define SM1_BYTES (SM1_FLOATS * 4 + 64 * 4)

__global__ void __launch_bounds__(256, 1)
fwd1_kernel(const float* __restrict__ x, const int* __restrict__ seg,
            const float* __restrict__ n1w, const float* __restrict__ n1b,
            const float* __restrict__ w1, const float* __restrict__ b1,
            const float* __restrict__ n2w, const float* __restrict__ n2b,
            float* __restrict__ z1out, float* __restrict__ z2out,
            float* __restrict__ segsum, float* __restrict__ segcnt) {
    extern __shared__ float sm[];
    float* sxn = sm;                          // [64][S_XN] normalized x (tf32)
    float* swt = sxn + 64 * S_XN;             // [128][S_WT] w1 chunk (tf32)
    float* sz2 = swt + 128 * S_WT;            // [64][S_Z2] staging / z2
    int*   ssg = (int*)(sz2 + 64 * S_Z2);     // [64]

    const int tid = threadIdx.x;
    const int wid = tid >> 5;
    const int lane = tid & 31;
    const int g = lane >> 2;    // groupID 0..7
    const int t = lane & 3;     // tid-in-group 0..3
    const int wm = wid & 1;     // warp m-group (2 x 32 rows)
    const int wn = wid >> 1;    // warp n-group (4 x 32 cols)
    const int row0 = blockIdx.x * 64;

    // ---- Phase 1: LayerNorm1 -> sxn (tf32-rounded)
    {
        float4 wv = __ldg(((const float4*)n1w) + lane);
        float4 bv = __ldg(((const float4*)n1b) + lane);
#pragma unroll
        for (int tt = 0; tt < 8; tt++) {
            int rl = wid * 8 + tt;
            size_t row = (size_t)(row0 + rl);
            float4 xv = __ldg((const float4*)(x + row * DDIM + lane * 4));
            float s  = warp_sum(xv.x + xv.y + xv.z + xv.w);
            float sq = warp_sum(xv.x * xv.x + xv.y * xv.y + xv.z * xv.z + xv.w * xv.w);
            float m = s * (1.f / 128.f);
            float var = sq * (1.f / 128.f) - m * m;
            float inv = rsqrtf(var + LN_EPS);
            float* dst = &sxn[rl * S_XN + lane * 4];
            dst[0] = tf32f((xv.x - m) * inv * wv.x + bv.x);
            dst[1] = tf32f((xv.y - m) * inv * wv.y + bv.y);
            dst[2] = tf32f((xv.z - m) * inv * wv.z + bv.z);
            dst[3] = tf32f((xv.w - m) * inv * wv.w + bv.w);
        }
    }
    if (tid < 64) ssg[tid] = __ldg(seg + row0 + tid);

    // ---- Phase 2: GEMM1 in 4 N-chunks of 128 via tf32 mma
#pragma unroll 1
    for (int c = 0; c < 4; c++) {
        __syncthreads();
        // stage w1 chunk [128][128] -> swt (tf32), coalesced float4 reads
        {
            const int cbase = c * 128;
#pragma unroll
            for (int q = 0; q < 16; q++) {
                int f4 = q * 256 + tid;
                int k = f4 >> 5;
                int n4 = f4 & 31;
                float4 v = __ldg((const float4*)(w1 + (size_t)k * FDIM + cbase + n4 * 4));
                v.x = tf32f(v.x); v.y = tf32f(v.y); v.z = tf32f(v.z); v.w = tf32f(v.w);
                *(float4*)(&swt[k * S_WT + n4 * 4]) = v;
            }
        }
        __syncthreads();

        float acc[2][4][4];
#pragma unroll
        for (int mt = 0; mt < 2; mt++)
#pragma unroll
            for (int nt = 0; nt < 4; nt++)
#pragma unroll
                for (int j = 0; j < 4; j++) acc[mt][nt][j] = 0.f;

#pragma unroll 2
        for (int k0 = 0; k0 < 128; k0 += 8) {
            unsigned a[2][4];
#pragma unroll
            for (int mt = 0; mt < 2; mt++) {
                int m0 = wm * 32 + mt * 16;
                a[mt][0] = __float_as_uint(sxn[(m0 + g) * S_XN + k0 + t]);
                a[mt][1] = __float_as_uint(sxn[(m0 + 8 + g) * S_XN + k0 + t]);
                a[mt][2] = __float_as_uint(sxn[(m0 + g) * S_XN + k0 + t + 4]);
                a[mt][3] = __float_as_uint(sxn[(m0 + 8 + g) * S_XN + k0 + t + 4]);
            }
#pragma unroll
            for (int nt = 0; nt < 4; nt++) {
                int n0 = wn * 32 + nt * 8;
                unsigned b0 = __float_as_uint(swt[(k0 + t) * S_WT + n0 + g]);
                unsigned b1v = __float_as_uint(swt[(k0 + t + 4) * S_WT + n0 + g]);
                mma_tf32(acc[0][nt], a[0], b0, b1v);
                mma_tf32(acc[1][nt], a[1], b0, b1v);
            }
        }

        // epilogue: bias + SELU -> sz2 staging
        const int cbase = c * 128;
        const int coff = (c < 2) ? 0 : (c - 2) * 128;
#pragma unroll
        for (int nt = 0; nt < 4; nt++) {
            int colL = wn * 32 + nt * 8 + 2 * t;
            float bx = __ldg(b1 + cbase + colL);
            float by = __ldg(b1 + cbase + colL + 1);
#pragma unroll
            for (int mt = 0; mt < 2; mt++) {
                int rA = wm * 32 + mt * 16 + g;
                sz2[rA * S_Z2 + coff + colL]           = selu_f(acc[mt][nt][0] + bx);
                sz2[rA * S_Z2 + coff + colL + 1]       = selu_f(acc[mt][nt][1] + by);
                sz2[(rA + 8) * S_Z2 + coff + colL]     = selu_f(acc[mt][nt][2] + bx);
                sz2[(rA + 8) * S_Z2 + coff + colL + 1] = selu_f(acc[mt][nt][3] + by);
            }
        }
        __syncthreads();

        if (c < 2) {
            // flush z1 chunk to gmem, coalesced
#pragma unroll
            for (int i = 0; i < 32; i++) {
                int idx = i * 256 + tid;
                int r = idx >> 7;
                int cc = idx & 127;
                z1out[(size_t)(row0 + r) * HDIM + c * 128 + cc] = sz2[r * S_Z2 + cc];
            }
        }
    }

    // ---- Phase 3: LayerNorm2 over z2 rows (256 wide), write gmem + smem
    {
        float wreg[8], breg[8];
#pragma unroll
        for (int u = 0; u < 8; u++) {
            wreg[u] = __ldg(n2w + lane + 32 * u);
            breg[u] = __ldg(n2b + lane + 32 * u);
        }
#pragma unroll
        for (int tt = 0; tt < 8; tt++) {
            int rl = wid * 8 + tt;
            float v[8];
            float s = 0.f, sq = 0.f;
#pragma unroll
            for (int u = 0; u < 8; u++) {
                v[u] = sz2[rl * S_Z2 + lane + 32 * u];
                s += v[u];
                sq += v[u] * v[u];
            }
            s = warp_sum(s);
            sq = warp_sum(sq);
            float m = s * (1.f / 256.f);
            float var = sq * (1.f / 256.f) - m * m;
            float inv = rsqrtf(var + LN_EPS);
            size_t row = (size_t)(row0 + rl);
#pragma unroll
            for (int u = 0; u < 8; u++) {
                float y = (v[u] - m) * inv * wreg[u] + breg[u];
                z2out[row * HDIM + lane + 32 * u] = y;
                sz2[rl * S_Z2 + lane + 32 * u] = y;
            }
        }
    }
    __syncthreads();

    // ---- Phase 4: run-length aggregated segment sums (segs sorted)
    {
        int col = tid;  // 0..255 == HDIM
        float acc = 0.f;
        int cur = ssg[0];
#pragma unroll 1
        for (int r = 0; r < 64; r++) {
            int s = ssg[r];
            if (s != cur) {
                atomicAdd(&segsum[(size_t)cur * HDIM + col], acc);
                acc = 0.f;
                cur = s;
            }
            acc += sz2[r * S_Z2 + col];
        }
        atomicAdd(&segsum[(size_t)cur * HDIM + col], acc);
    }
    if (tid == 0) {
        float acc = 0.f;
        int cur = ssg[0];
        for (int r = 0; r < 64; r++) {
            int s = ssg[r];
            if (s != cur) {
                atomicAdd(&segcnt[cur], acc);
                acc = 0.f;
                cur = s;
            }
            acc += 1.f;
        }
        atomicAdd(&segcnt[cur], acc);
    }
}

// ---------------- Kernel 2: per-(batch,h) gate coefficients ----------------
__global__ void coeff_kernel(const float* __restrict__ sum_r, const float* __restrict__ cnt_r,
                             const float* __restrict__ sum_a, const float* __restrict__ cnt_a,
                             const float* __restrict__ ref_reg, const float* __restrict__ reg_w_pre,
                             const float* __restrict__ beta_ref, const float* __restrict__ beta_alt,
                             const float* __restrict__ gamma,
                             float* __restrict__ cref, float* __restrict__ calt) {
    int idx = blockIdx.x * blockDim.x + threadIdx.x;
    if (idx >= BSEG * HDIM) return;
    int b = idx >> 8;
    int h = idx & 255;
    float rw = expf(reg_w_pre[0]) + 0.25f;
    float rmf = (sum_r[idx] + rw * ref_reg[h]) / (cnt_r[b] + rw);
    float amf = sum_a[idx] / fmaxf(cnt_a[b], 1.f);
    cref[idx] = beta_ref[0] * rmf;
    calt[idx] = beta_alt[0] * amf + gamma[0] * rmf;
}

// ---------------- Kernel 3: gate + GEMM2(tf32 mma) + residual --------------
// Block: 256 threads (8 warps), 64 rows.
#define SM2_FLOATS (256 * S_WT + 64 * S_Z2)
#define SM2_BYTES (SM2_FLOATS * 4 + 64 * 4)

__global__ void __launch_bounds__(256, 1)
fwd2_kernel(const float* __restrict__ x, const int* __restrict__ seg,
            const float* __restrict__ z1, const float* __restrict__ z2,
            const float* __restrict__ ctab, const float* __restrict__ alpha_p,
            const float* __restrict__ w2, const float* __restrict__ b2,
            float* __restrict__ out) {
    extern __shared__ float sm[];
    float* sw2 = sm;                          // [256][S_WT] (tf32)
    float* sg  = sw2 + 256 * S_WT;            // [64][S_Z2] gated acts (tf32)
    int*   ssg = (int*)(sg + 64 * S_Z2);      // [64]

    const int tid = threadIdx.x;
    const int lane = tid & 31;
    const int wid = tid >> 5;
    const int g = lane >> 2;
    const int t = lane & 3;
    const int wm = wid & 1;
    const int wn = wid >> 1;
    const int row0 = blockIdx.x * 64;

    // stage full W2 (256x128) -> sw2 (tf32), coalesced
#pragma unroll
    for (int q = 0; q < 32; q++) {
        int f4 = q * 256 + tid;
        int k = f4 >> 5;
        int n4 = f4 & 31;
        float4 v = __ldg((const float4*)(w2 + (size_t)k * DDIM + n4 * 4));
        v.x = tf32f(v.x); v.y = tf32f(v.y); v.z = tf32f(v.z); v.w = tf32f(v.w);
        *(float4*)(&sw2[k * S_WT + n4 * 4]) = v;
    }
    if (tid < 64) ssg[tid] = __ldg(seg + row0 + tid);
    __syncthreads();

    // build gated activations g = z1 * (z2*alpha + 1 + c[seg]) (tf32)
    const float alpha = __ldg(alpha_p);
#pragma unroll 4
    for (int it = 0; it < 64; it++) {
        size_t row = (size_t)(row0 + it);
        float z1v = __ldg(z1 + row * HDIM + tid);
        float z2v = __ldg(z2 + row * HDIM + tid);
        float cc = __ldg(ctab + (size_t)ssg[it] * HDIM + tid);
        sg[it * S_Z2 + tid] = tf32f(z1v * fmaf(z2v, alpha, 1.f + cc));
    }
    __syncthreads();

    // GEMM: out[64][128] = g[64][256] @ w2[256][128] via tf32 mma
    float acc[2][4][4];
#pragma unroll
    for (int mt = 0; mt < 2; mt++)
#pragma unroll
        for (int nt = 0; nt < 4; nt++)
#pragma unroll
            for (int j = 0; j < 4; j++) acc[mt][nt][j] = 0.f;

#pragma unroll 2
    for (int k0 = 0; k0 < 256; k0 += 8) {
        unsigned a[2][4];
#pragma unroll
        for (int mt = 0; mt < 2; mt++) {
            int m0 = wm * 32 + mt * 16;
            a[mt][0] = __float_as_uint(sg[(m0 + g) * S_Z2 + k0 + t]);
            a[mt][1] = __float_as_uint(sg[(m0 + 8 + g) * S_Z2 + k0 + t]);
            a[mt][2] = __float_as_uint(sg[(m0 + g) * S_Z2 + k0 + t + 4]);
            a[mt][3] = __float_as_uint(sg[(m0 + 8 + g) * S_Z2 + k0 + t + 4]);
        }
#pragma unroll
        for (int nt = 0; nt < 4; nt++) {
            int n0 = wn * 32 + nt * 8;
            unsigned b0 = __float_as_uint(sw2[(k0 + t) * S_WT + n0 + g]);
            unsigned b1v = __float_as_uint(sw2[(k0 + t + 4) * S_WT + n0 + g]);
            mma_tf32(acc[0][nt], a[0], b0, b1v);
            mma_tf32(acc[1][nt], a[1], b0, b1v);
        }
    }

    // epilogue: residual + bias, float2 stores
#pragma unroll
    for (int nt = 0; nt < 4; nt++) {
        int col = wn * 32 + nt * 8 + 2 * t;
        float bx = __ldg(b2 + col);
        float by = __ldg(b2 + col + 1);
#pragma unroll
        for (int mt = 0; mt < 2; mt++) {
            size_t rowA = (size_t)(row0 + wm * 32 + mt * 16 + g);
            size_t rowB = rowA + 8;
            float2 xa = __ldg((const float2*)(x + rowA * DDIM + col));
            float2 xb = __ldg((const float2*)(x + rowB * DDIM + col));
            float2 oa, ob;
            oa.x = xa.x + acc[mt][nt][0] + bx;
            oa.y = xa.y + acc[mt][nt][1] + by;
            ob.x = xb.x + acc[mt][nt][2] + bx;
            ob.y = xb.y + acc[mt][nt][3] + by;
            *(float2*)(out + rowA * DDIM + col) = oa;
            *(float2*)(out + rowB * DDIM + col) = ob;
        }
    }
}

// ---------------- Launch ----------------
extern "C" void kernel_launch(void* const* d_in, const int* in_sizes, int n_in,
                              void* d_out, int out_size) {
    const float* ref_flat = (const float*)d_in[0];
    const float* alt_flat = (const float*)d_in[1];
    const int*   ref_seg  = (const int*)d_in[2];
    const int*   alt_seg  = (const int*)d_in[3];
    const float* norm1_w  = (const float*)d_in[4];
    const float* norm1_b  = (const float*)d_in[5];
    const float* w1_ref   = (const float*)d_in[6];
    const float* b1_ref   = (const float*)d_in[7];
    const float* w1_alt   = (const float*)d_in[8];
    const float* b1_alt   = (const float*)d_in[9];
    const float* norm2_w  = (const float*)d_in[10];
    const float* norm2_b  = (const float*)d_in[11];
    const float* alpha_ref = (const float*)d_in[12];
    const float* alpha_alt = (const float*)d_in[13];
    const float* beta_ref  = (const float*)d_in[14];
    const float* beta_alt  = (const float*)d_in[15];
    const float* gamma     = (const float*)d_in[16];
    const float* ref_regularizer = (const float*)d_in[17];
    const float* reg_w_pre = (const float*)d_in[18];
    const float* w2_ref    = (const float*)d_in[19];
    const float* b2_ref    = (const float*)d_in[20];
    const float* w2_alt    = (const float*)d_in[21];
    const float* b2_alt    = (const float*)d_in[22];

    float* out_r = (float*)d_out;
    float* out_a = out_r + (size_t)NREF * DDIM;

    float *pz1r, *pz2r, *pz1a, *pz2a, *psr, *psa, *pcr, *pca, *pcref, *pcalt;
    cudaGetSymbolAddress((void**)&pz1r, g_z1_ref);
    cudaGetSymbolAddress((void**)&pz2r, g_z2_ref);
    cudaGetSymbolAddress((void**)&pz1a, g_z1_alt);
    cudaGetSymbolAddress((void**)&pz2a, g_z2_alt);
    cudaGetSymbolAddress((void**)&psr,  g_sum_ref);
    cudaGetSymbolAddress((void**)&psa,  g_sum_alt);
    cudaGetSymbolAddress((void**)&pcr,  g_cnt_ref);
    cudaGetSymbolAddress((void**)&pca,  g_cnt_alt);
    cudaGetSymbolAddress((void**)&pcref, g_cref);
    cudaGetSymbolAddress((void**)&pcalt, g_calt);

    cudaFuncSetAttribute(fwd1_kernel, cudaFuncAttributeMaxDynamicSharedMemorySize, SM1_BYTES);
    cudaFuncSetAttribute(fwd2_kernel, cudaFuncAttributeMaxDynamicSharedMemorySize, SM2_BYTES);

    zero_kernel<<<(BSEG * HDIM + 255) / 256, 256>>>(psr, psa, pcr, pca);

    fwd1_kernel<<<NREF / 64, 256, SM1_BYTES>>>(ref_flat, ref_seg, norm1_w, norm1_b,
                                               w1_ref, b1_ref, norm2_w, norm2_b,
                                               pz1r, pz2r, psr, pcr);
    fwd1_kernel<<<NALT / 64, 256, SM1_BYTES>>>(alt_flat, alt_seg, norm1_w, norm1_b,
                                               w1_alt, b1_alt, norm2_w, norm2_b,
                                               pz1a, pz2a, psa, pca);

    coeff_kernel<<<(BSEG * HDIM + 255) / 256, 256>>>(psr, pcr, psa, pca,
                                                     ref_regularizer, reg_w_pre,
                                                     beta_ref, beta_alt, gamma,
                                                     pcref, pcalt);

    fwd2_kernel<<<NREF / 64, 256, SM2_BYTES>>>(ref_flat, ref_seg, pz1r, pz2r,
                                               pcref, alpha_ref, w2_ref, b2_ref, out_r);
    fwd2_kernel<<<NALT / 64, 256, SM2_BYTES>>>(alt_flat, alt_seg, pz1a, pz2a,
                                               pcalt, alpha_alt, w2_alt, b2_alt, out_a);
}

// round 4
// speedup vs baseline: 4.5848x; 2.9575x over previous
#include <cuda_runtime.h>
#include <cuda_bf16.h>
#include <math.h>

// ---------------- Problem constants ----------------
#define NREF 131072
#define NALT 32768
#define BSEG 4096
#define DDIM 128
#define FDIM 512
#define HDIM 256
#define LN_EPS 1e-5f

typedef unsigned int u32;

// ---------------- Scratch (device globals) ----------------
__device__ u32 g_z1_ref[(size_t)NREF * 128];   // bf16x2 pairs (256 cols)
__device__ u32 g_z2_ref[(size_t)NREF * 128];
__device__ u32 g_z1_alt[(size_t)NALT * 128];
__device__ u32 g_z2_alt[(size_t)NALT * 128];
__device__ float g_sum_ref[BSEG * HDIM];
__device__ float g_sum_alt[BSEG * HDIM];
__device__ float g_cnt_ref[BSEG];
__device__ float g_cnt_alt[BSEG];
__device__ float g_cref[BSEG * HDIM];
__device__ float g_calt[BSEG * HDIM];

// ---------------- Helpers ----------------
__device__ __forceinline__ u32 pkbf(float lo, float hi) {
    u32 r;
    asm("cvt.rn.bf16x2.f32 %0, %1, %2;" : "=r"(r) : "f"(hi), "f"(lo));
    return r;
}
__device__ __forceinline__ float2 upbf(u32 v) {
    union { u32 u; __nv_bfloat162 h; } cv;
    cv.u = v;
    return __bfloat1622float2(cv.h);
}
__device__ __forceinline__ void mma_bf16(float* c, const u32* a, u32 b0, u32 b1) {
    asm volatile(
        "mma.sync.aligned.m16n8k16.row.col.f32.bf16.bf16.f32 "
        "{%0,%1,%2,%3}, {%4,%5,%6,%7}, {%8,%9}, {%0,%1,%2,%3};"
        : "+f"(c[0]), "+f"(c[1]), "+f"(c[2]), "+f"(c[3])
        : "r"(a[0]), "r"(a[1]), "r"(a[2]), "r"(a[3]), "r"(b0), "r"(b1));
}
__device__ __forceinline__ float warp_sum(float v) {
#pragma unroll
    for (int o = 16; o > 0; o >>= 1) v += __shfl_xor_sync(0xffffffffu, v, o);
    return v;
}
__device__ __forceinline__ float selu_f(float x) {
    const float sc = 1.0507009873554805f;
    const float al = 1.6732632423543772f;
    return x > 0.f ? sc * x : sc * al * (expf(x) - 1.f);
}

// ---------------- Kernel 0: zero accumulators ----------------
__global__ void zero_kernel(float* __restrict__ s1, float* __restrict__ s2,
                            float* __restrict__ c1, float* __restrict__ c2) {
    int i = blockIdx.x * blockDim.x + threadIdx.x;
    if (i < BSEG * HDIM) { s1[i] = 0.f; s2[i] = 0.f; }
    if (i < BSEG)        { c1[i] = 0.f; c2[i] = 0.f; }
}

// ---------------- Kernel 1: persistent LN1+GEMM1+SELU+LN2+segsum ----------
// 512 threads (16 warps). W1 bf16 resident in smem. Tile = 64 rows.
#define SW1_U (512 * 68)
#define SA_U  (64 * 68)
#define SZ_U  (64 * 132)
#define SM1_BYTES ((SW1_U + SA_U + SZ_U) * 4 + 64 * 8 * 2 * 4 + 64 * 4)

__global__ void __launch_bounds__(512, 1)
fwd1_kernel(const float* __restrict__ x, const int* __restrict__ seg,
            const float* __restrict__ n1w, const float* __restrict__ n1b,
            const float* __restrict__ w1, const float* __restrict__ b1,
            const float* __restrict__ n2w, const float* __restrict__ n2b,
            u32* __restrict__ z1out, u32* __restrict__ z2out,
            float* __restrict__ segsum, float* __restrict__ segcnt,
            int ntiles) {
    extern __shared__ float smf[];
    u32* sw = (u32*)smf;              // [512 n][68] bf16 k-pairs of W1
    u32* sa = sw + SW1_U;             // [64 m][68]  bf16 k-pairs of LN1(x)
    u32* sz = sa + SA_U;              // [64 m][132] bf16 col-pairs staging
    float* ps = (float*)(sz + SZ_U);  // [64][8] LN2 partial sums
    float* pq = ps + 64 * 8;          // [64][8] LN2 partial sumsq
    int*   ssg = (int*)(pq + 64 * 8); // [64]

    const int tid = threadIdx.x;
    const int lane = tid & 31;
    const int wid = tid >> 5;
    const int g = lane >> 2;
    const int t = lane & 3;
    const int wm = wid & 1;    // row half (32 rows)
    const int wn = wid >> 1;   // 8 col-groups of 32

    // ---- stage W1 (f32 gmem -> bf16-pair smem), once
    for (int i = tid; i < 64 * 512; i += 512) {
        int kp = i >> 9;
        int n = i & 511;
        float v0 = __ldg(w1 + (size_t)(2 * kp) * FDIM + n);
        float v1 = __ldg(w1 + (size_t)(2 * kp + 1) * FDIM + n);
        sw[n * 68 + kp] = pkbf(v0, v1);
    }

    // ---- hoist per-thread constants
    float4 wv = __ldg(((const float4*)n1w) + lane);
    float4 bv = __ldg(((const float4*)n1b) + lane);
    float b1r[2][4][2], w2r[4][2], b2r[4][2];
#pragma unroll
    for (int c = 0; c < 2; c++)
#pragma unroll
        for (int nt = 0; nt < 4; nt++) {
            int col = c * 256 + wn * 32 + nt * 8 + 2 * t;
            b1r[c][nt][0] = __ldg(b1 + col);
            b1r[c][nt][1] = __ldg(b1 + col + 1);
        }
#pragma unroll
    for (int nt = 0; nt < 4; nt++) {
        int col = wn * 32 + nt * 8 + 2 * t;
        w2r[nt][0] = __ldg(n2w + col);  w2r[nt][1] = __ldg(n2w + col + 1);
        b2r[nt][0] = __ldg(n2b + col);  b2r[nt][1] = __ldg(n2b + col + 1);
    }
    __syncthreads();

    for (int tile = blockIdx.x; tile < ntiles; tile += gridDim.x) {
        const int row0 = tile * 64;
        if (tid < 64) ssg[tid] = __ldg(seg + row0 + tid);

        // ---- LN1 -> sa (each warp: 4 rows)
#pragma unroll
        for (int rr = 0; rr < 4; rr++) {
            int rl = wid * 4 + rr;
            float4 xv = __ldg((const float4*)(x + (size_t)(row0 + rl) * DDIM) + lane);
            float s  = warp_sum(xv.x + xv.y + xv.z + xv.w);
            float sq = warp_sum(xv.x * xv.x + xv.y * xv.y + xv.z * xv.z + xv.w * xv.w);
            float m = s * (1.f / 128.f);
            float inv = rsqrtf(sq * (1.f / 128.f) - m * m + LN_EPS);
            float y0 = (xv.x - m) * inv * wv.x + bv.x;
            float y1 = (xv.y - m) * inv * wv.y + bv.y;
            float y2 = (xv.z - m) * inv * wv.z + bv.z;
            float y3 = (xv.w - m) * inv * wv.w + bv.w;
            *(uint2*)(sa + rl * 68 + lane * 2) = make_uint2(pkbf(y0, y1), pkbf(y2, y3));
        }
        __syncthreads();

        // ---- two N-chunks of 256: c=0 -> z1, c=1 -> z2(+LN2)
#pragma unroll 1
        for (int c = 0; c < 2; c++) {
            float acc[2][4][4];
#pragma unroll
            for (int mt = 0; mt < 2; mt++)
#pragma unroll
                for (int nt = 0; nt < 4; nt++)
#pragma unroll
                    for (int j = 0; j < 4; j++) acc[mt][nt][j] = 0.f;

            const int nb = c * 256 + wn * 32;
#pragma unroll
            for (int k0 = 0; k0 < 128; k0 += 16) {
                const int kp = k0 >> 1;
                u32 a[2][4];
#pragma unroll
                for (int mt = 0; mt < 2; mt++) {
                    const u32* pa = sa + (wm * 32 + mt * 16 + g) * 68 + kp + t;
                    a[mt][0] = pa[0];
                    a[mt][2] = pa[4];
                    a[mt][1] = pa[8 * 68];
                    a[mt][3] = pa[8 * 68 + 4];
                }
#pragma unroll
                for (int nt = 0; nt < 4; nt++) {
                    const u32* pb = sw + (nb + nt * 8 + g) * 68 + kp + t;
                    u32 b0 = pb[0], b1v = pb[4];
                    mma_bf16(acc[0][nt], a[0], b0, b1v);
                    mma_bf16(acc[1][nt], a[1], b0, b1v);
                }
            }

            // bias + SELU in place
#pragma unroll
            for (int mt = 0; mt < 2; mt++)
#pragma unroll
                for (int nt = 0; nt < 4; nt++) {
                    acc[mt][nt][0] = selu_f(acc[mt][nt][0] + b1r[c][nt][0]);
                    acc[mt][nt][1] = selu_f(acc[mt][nt][1] + b1r[c][nt][1]);
                    acc[mt][nt][2] = selu_f(acc[mt][nt][2] + b1r[c][nt][0]);
                    acc[mt][nt][3] = selu_f(acc[mt][nt][3] + b1r[c][nt][1]);
                }

            if (c == 0) {
                // z1: pack to sz, flush coalesced as bf16 pairs
#pragma unroll
                for (int mt = 0; mt < 2; mt++)
#pragma unroll
                    for (int nt = 0; nt < 4; nt++) {
                        int r = wm * 32 + mt * 16 + g;
                        int c2 = wn * 16 + nt * 4 + t;
                        sz[r * 132 + c2]       = pkbf(acc[mt][nt][0], acc[mt][nt][1]);
                        sz[(r + 8) * 132 + c2] = pkbf(acc[mt][nt][2], acc[mt][nt][3]);
                    }
                __syncthreads();
                for (int i = tid; i < 64 * 128; i += 512) {
                    int r = i >> 7, c2 = i & 127;
                    z1out[((size_t)(row0 + r) << 7) + c2] = sz[r * 132 + c2];
                }
                __syncthreads();
            } else {
                // z2: LN2 (cross-warp row reduction), pack, flush, then segsum
                float s[2][2], q[2][2];
#pragma unroll
                for (int mt = 0; mt < 2; mt++) {
                    s[mt][0] = s[mt][1] = q[mt][0] = q[mt][1] = 0.f;
#pragma unroll
                    for (int nt = 0; nt < 4; nt++) {
                        s[mt][0] += acc[mt][nt][0] + acc[mt][nt][1];
                        q[mt][0] += acc[mt][nt][0] * acc[mt][nt][0] + acc[mt][nt][1] * acc[mt][nt][1];
                        s[mt][1] += acc[mt][nt][2] + acc[mt][nt][3];
                        q[mt][1] += acc[mt][nt][2] * acc[mt][nt][2] + acc[mt][nt][3] * acc[mt][nt][3];
                    }
                }
#pragma unroll
                for (int off = 1; off <= 2; off <<= 1)
#pragma unroll
                    for (int mt = 0; mt < 2; mt++)
#pragma unroll
                        for (int h = 0; h < 2; h++) {
                            s[mt][h] += __shfl_xor_sync(0xffffffffu, s[mt][h], off);
                            q[mt][h] += __shfl_xor_sync(0xffffffffu, q[mt][h], off);
                        }
                if (t == 0) {
#pragma unroll
                    for (int mt = 0; mt < 2; mt++)
#pragma unroll
                        for (int h = 0; h < 2; h++) {
                            int r = wm * 32 + mt * 16 + g + 8 * h;
                            ps[r * 8 + wn] = s[mt][h];
                            pq[r * 8 + wn] = q[mt][h];
                        }
                }
                __syncthreads();
                float mean[2][2], inv[2][2];
#pragma unroll
                for (int mt = 0; mt < 2; mt++)
#pragma unroll
                    for (int h = 0; h < 2; h++) {
                        int r = wm * 32 + mt * 16 + g + 8 * h;
                        float S = 0.f, Q = 0.f;
#pragma unroll
                        for (int w = 0; w < 8; w++) { S += ps[r * 8 + w]; Q += pq[r * 8 + w]; }
                        float m = S * (1.f / 256.f);
                        mean[mt][h] = m;
                        inv[mt][h] = rsqrtf(Q * (1.f / 256.f) - m * m + LN_EPS);
                    }
#pragma unroll
                for (int mt = 0; mt < 2; mt++)
#pragma unroll
                    for (int nt = 0; nt < 4; nt++) {
                        int r = wm * 32 + mt * 16 + g;
                        int c2 = wn * 16 + nt * 4 + t;
                        float y0 = (acc[mt][nt][0] - mean[mt][0]) * inv[mt][0] * w2r[nt][0] + b2r[nt][0];
                        float y1 = (acc[mt][nt][1] - mean[mt][0]) * inv[mt][0] * w2r[nt][1] + b2r[nt][1];
                        float y2 = (acc[mt][nt][2] - mean[mt][1]) * inv[mt][1] * w2r[nt][0] + b2r[nt][0];
                        float y3 = (acc[mt][nt][3] - mean[mt][1]) * inv[mt][1] * w2r[nt][1] + b2r[nt][1];
                        sz[r * 132 + c2]       = pkbf(y0, y1);
                        sz[(r + 8) * 132 + c2] = pkbf(y2, y3);
                    }
                __syncthreads();
                for (int i = tid; i < 64 * 128; i += 512) {
                    int r = i >> 7, c2 = i & 127;
                    z2out[((size_t)(row0 + r) << 7) + c2] = sz[r * 132 + c2];
                }
            }
        }

        // ---- segment sums from sz (z2), run-length aggregated (seg sorted)
        {
            int grp = tid >> 8;         // 0,1 -> rows 0-31 / 32-63
            int col = tid & 255;
            int rb = grp * 32;
            float accv = 0.f, cnt = 0.f;
            int cur = ssg[rb];
#pragma unroll 1
            for (int r = rb; r < rb + 32; r++) {
                int sv = ssg[r];
                if (sv != cur) {
                    atomicAdd(&segsum[(size_t)cur * HDIM + col], accv);
                    if (col == 0) atomicAdd(&segcnt[cur], cnt);
                    accv = 0.f; cnt = 0.f; cur = sv;
                }
                float2 pv = upbf(sz[r * 132 + (col >> 1)]);
                accv += (col & 1) ? pv.y : pv.x;
                cnt += 1.f;
            }
            atomicAdd(&segsum[(size_t)cur * HDIM + col], accv);
            if (col == 0) atomicAdd(&segcnt[cur], cnt);
        }
        __syncthreads();
    }
}

// ---------------- Kernel 2: per-(batch,h) gate coefficients ----------------
__global__ void coeff_kernel(const float* __restrict__ sum_r, const float* __restrict__ cnt_r,
                             const float* __restrict__ sum_a, const float* __restrict__ cnt_a,
                             const float* __restrict__ ref_reg, const float* __restrict__ reg_w_pre,
                             const float* __restrict__ beta_ref, const float* __restrict__ beta_alt,
                             const float* __restrict__ gamma,
                             float* __restrict__ cref, float* __restrict__ calt) {
    int idx = blockIdx.x * blockDim.x + threadIdx.x;
    if (idx >= BSEG * HDIM) return;
    int b = idx >> 8;
    int h = idx & 255;
    float rw = expf(reg_w_pre[0]) + 0.25f;
    float rmf = (sum_r[idx] + rw * ref_reg[h]) / (cnt_r[b] + rw);
    float amf = sum_a[idx] / fmaxf(cnt_a[b], 1.f);
    cref[idx] = beta_ref[0] * rmf;
    calt[idx] = beta_alt[0] * amf + gamma[0] * rmf;
}

// ---------------- Kernel 3: persistent gate+GEMM2+residual ----------------
// 512 threads, 2 CTA/SM. W2 bf16 resident (67.6KB). Tile = 64 rows.
#define SW2_U (128 * 132)
#define SG_U  (64 * 132)
#define SM2_BYTES ((SW2_U + SG_U) * 4 + 64 * 4)

__global__ void __launch_bounds__(512, 2)
fwd2_kernel(const float* __restrict__ x, const int* __restrict__ seg,
            const u32* __restrict__ z1, const u32* __restrict__ z2,
            const float* __restrict__ ctab, const float* __restrict__ alpha_p,
            const float* __restrict__ w2, const float* __restrict__ b2,
            float* __restrict__ out, int ntiles) {
    extern __shared__ float smf[];
    u32* sw = (u32*)smf;            // [128 n][132] bf16 k-pairs of W2
    u32* sg = sw + SW2_U;           // [64 m][132]  gated activations
    int* ssg = (int*)(sg + SG_U);   // [64]

    const int tid = threadIdx.x;
    const int lane = tid & 31;
    const int wid = tid >> 5;
    const int g = lane >> 2;
    const int t = lane & 3;
    const int wm = wid & 3;    // 4 row-groups of 16
    const int wn = wid >> 2;   // 4 col-groups of 32

    // stage W2 (f32 gmem -> bf16-pair smem), once
    for (int i = tid; i < 128 * 128; i += 512) {
        int kp = i >> 7;
        int n = i & 127;
        float v0 = __ldg(w2 + (size_t)(2 * kp) * DDIM + n);
        float v1 = __ldg(w2 + (size_t)(2 * kp + 1) * DDIM + n);
        sw[n * 132 + kp] = pkbf(v0, v1);
    }
    float b2r[4][2];
#pragma unroll
    for (int nt = 0; nt < 4; nt++) {
        int col = wn * 32 + nt * 8 + 2 * t;
        b2r[nt][0] = __ldg(b2 + col);
        b2r[nt][1] = __ldg(b2 + col + 1);
    }
    const float alpha = __ldg(alpha_p);
    __syncthreads();

    const float2* ctab2 = (const float2*)ctab;
    const float2* x2 = (const float2*)x;
    float2* out2 = (float2*)out;

    for (int tile = blockIdx.x; tile < ntiles; tile += gridDim.x) {
        const int row0 = tile * 64;
        if (tid < 64) ssg[tid] = __ldg(seg + row0 + tid);
        __syncthreads();

        // build gated activations -> sg (bf16 pairs)
#pragma unroll 4
        for (int i = tid; i < 64 * 128; i += 512) {
            int r = i >> 7, c2 = i & 127;
            size_t gidx = ((size_t)(row0 + r) << 7) + c2;
            float2 z1f = upbf(__ldg(z1 + gidx));
            float2 z2f = upbf(__ldg(z2 + gidx));
            float2 cc = __ldg(ctab2 + ((size_t)ssg[r] << 7) + c2);
            float g0 = z1f.x * fmaf(z2f.x, alpha, 1.f + cc.x);
            float g1 = z1f.y * fmaf(z2f.y, alpha, 1.f + cc.y);
            sg[r * 132 + c2] = pkbf(g0, g1);
        }
        __syncthreads();

        // GEMM: out[64][128] = g[64][256] @ W2, warp tile 16x32
        float acc[4][4];
#pragma unroll
        for (int nt = 0; nt < 4; nt++)
#pragma unroll
            for (int j = 0; j < 4; j++) acc[nt][j] = 0.f;

#pragma unroll
        for (int k0 = 0; k0 < 256; k0 += 16) {
            const int kp = k0 >> 1;
            u32 a[4];
            const u32* pa = sg + (wm * 16 + g) * 132 + kp + t;
            a[0] = pa[0];
            a[2] = pa[4];
            a[1] = pa[8 * 132];
            a[3] = pa[8 * 132 + 4];
#pragma unroll
            for (int nt = 0; nt < 4; nt++) {
                const u32* pb = sw + (wn * 32 + nt * 8 + g) * 132 + kp + t;
                mma_bf16(acc[nt], a, pb[0], pb[4]);
            }
        }

        // epilogue: residual + bias (32B-contiguous float2 per row-quad)
#pragma unroll
        for (int nt = 0; nt < 4; nt++) {
            int col2 = (wn * 32 + nt * 8 + 2 * t) >> 1;
            size_t rowA = (size_t)(row0 + wm * 16 + g);
            size_t rowB = rowA + 8;
            float2 xa = __ldg(x2 + rowA * 64 + col2);
            float2 xb = __ldg(x2 + rowB * 64 + col2);
            float2 oa, ob;
            oa.x = xa.x + acc[nt][0] + b2r[nt][0];
            oa.y = xa.y + acc[nt][1] + b2r[nt][1];
            ob.x = xb.x + acc[nt][2] + b2r[nt][0];
            ob.y = xb.y + acc[nt][3] + b2r[nt][1];
            out2[rowA * 64 + col2] = oa;
            out2[rowB * 64 + col2] = ob;
        }
        __syncthreads();
    }
}

// ---------------- Launch ----------------
extern "C" void kernel_launch(void* const* d_in, const int* in_sizes, int n_in,
                              void* d_out, int out_size) {
    const float* ref_flat = (const float*)d_in[0];
    const float* alt_flat = (const float*)d_in[1];
    const int*   ref_seg  = (const int*)d_in[2];
    const int*   alt_seg  = (const int*)d_in[3];
    const float* norm1_w  = (const float*)d_in[4];
    const float* norm1_b  = (const float*)d_in[5];
    const float* w1_ref   = (const float*)d_in[6];
    const float* b1_ref   = (const float*)d_in[7];
    const float* w1_alt   = (const float*)d_in[8];
    const float* b1_alt   = (const float*)d_in[9];
    const float* norm2_w  = (const float*)d_in[10];
    const float* norm2_b  = (const float*)d_in[11];
    const float* alpha_ref = (const float*)d_in[12];
    const float* alpha_alt = (const float*)d_in[13];
    const float* beta_ref  = (const float*)d_in[14];
    const float* beta_alt  = (const float*)d_in[15];
    const float* gamma     = (const float*)d_in[16];
    const float* ref_regularizer = (const float*)d_in[17];
    const float* reg_w_pre = (const float*)d_in[18];
    const float* w2_ref    = (const float*)d_in[19];
    const float* b2_ref    = (const float*)d_in[20];
    const float* w2_alt    = (const float*)d_in[21];
    const float* b2_alt    = (const float*)d_in[22];

    float* out_r = (float*)d_out;
    float* out_a = out_r + (size_t)NREF * DDIM;

    u32 *pz1r, *pz2r, *pz1a, *pz2a;
    float *psr, *psa, *pcr, *pca, *pcref, *pcalt;
    cudaGetSymbolAddress((void**)&pz1r, g_z1_ref);
    cudaGetSymbolAddress((void**)&pz2r, g_z2_ref);
    cudaGetSymbolAddress((void**)&pz1a, g_z1_alt);
    cudaGetSymbolAddress((void**)&pz2a, g_z2_alt);
    cudaGetSymbolAddress((void**)&psr,  g_sum_ref);
    cudaGetSymbolAddress((void**)&psa,  g_sum_alt);
    cudaGetSymbolAddress((void**)&pcr,  g_cnt_ref);
    cudaGetSymbolAddress((void**)&pca,  g_cnt_alt);
    cudaGetSymbolAddress((void**)&pcref, g_cref);
    cudaGetSymbolAddress((void**)&pcalt, g_calt);

    int sm_count = 148;
    cudaDeviceGetAttribute(&sm_count, cudaDevAttrMultiProcessorCount, 0);

    cudaFuncSetAttribute(fwd1_kernel, cudaFuncAttributeMaxDynamicSharedMemorySize, SM1_BYTES);
    cudaFuncSetAttribute(fwd2_kernel, cudaFuncAttributeMaxDynamicSharedMemorySize, SM2_BYTES);

    zero_kernel<<<(BSEG * HDIM + 255) / 256, 256>>>(psr, psa, pcr, pca);

    fwd1_kernel<<<sm_count, 512, SM1_BYTES>>>(ref_flat, ref_seg, norm1_w, norm1_b,
                                              w1_ref, b1_ref, norm2_w, norm2_b,
                                              pz1r, pz2r, psr, pcr, NREF / 64);
    fwd1_kernel<<<sm_count, 512, SM1_BYTES>>>(alt_flat, alt_seg, norm1_w, norm1_b,
                                              w1_alt, b1_alt, norm2_w, norm2_b,
                                              pz1a, pz2a, psa, pca, NALT / 64);

    coeff_kernel<<<(BSEG * HDIM + 255) / 256, 256>>>(psr, pcr, psa, pca,
                                                     ref_regularizer, reg_w_pre,
                                                     beta_ref, beta_alt, gamma,
                                                     pcref, pcalt);

    fwd2_kernel<<<2 * sm_count, 512, SM2_BYTES>>>(ref_flat, ref_seg, pz1r, pz2r,
                                                  pcref, alpha_ref, w2_ref, b2_ref,
                                                  out_r, NREF / 64);
    fwd2_kernel<<<2 * sm_count, 512, SM2_BYTES>>>(alt_flat, alt_seg, pz1a, pz2a,
                                                  pcalt, alpha_alt, w2_alt, b2_alt,
                                                  out_a, NALT / 64);
}